// round 1
// baseline (speedup 1.0000x reference)
#include <cuda_runtime.h>
#include <cuda_bf16.h>

#define S_LEN 2048
#define D_DIM 1024
#define NH    16
#define HDIM  64
#define NB    2
#define M_TOT (NB * S_LEN)   // 4096

// Scratch (static device globals; no runtime allocation allowed)
__device__ float g_q[NB * NH * HDIM * S_LEN];   // [b,h,hd,s]  (transposed for attention)
__device__ float g_k[NB * NH * HDIM * S_LEN];   // [b,h,hd,s]
__device__ float g_v[NB * NH * S_LEN * HDIM];   // [b,h,s,hd]
__device__ float g_ctx[NB * S_LEN * D_DIM];     // [b,s,h,hd] == [b,s,d]

// ---------------------------------------------------------------------------
// Kernel 1: fused QKV projection.  y[n,o] = sum_d x[n,d] * W[o,d]
// grid = (N/128, M/128, 3), 256 threads, 128x128x16 tile, 8x8 per thread.
// ---------------------------------------------------------------------------
__global__ __launch_bounds__(256) void qkv_kernel(
    const float* __restrict__ x,  const float* __restrict__ wq,
    const float* __restrict__ wk, const float* __restrict__ wv)
{
    __shared__ float As[16][132];
    __shared__ float Bs[16][132];

    const float* w = (blockIdx.z == 0) ? wq : ((blockIdx.z == 1) ? wk : wv);
    const int m0 = blockIdx.y * 128;
    const int n0 = blockIdx.x * 128;
    const int tid = threadIdx.x;
    const int tx = tid & 15, ty = tid >> 4;
    const int lr = tid >> 2, lk = (tid & 3) << 2;

    float acc[8][8];
    #pragma unroll
    for (int i = 0; i < 8; i++)
        #pragma unroll
        for (int j = 0; j < 8; j++) acc[i][j] = 0.f;

    for (int k0 = 0; k0 < D_DIM; k0 += 16) {
        float4 a0 = *(const float4*)(x + (size_t)(m0 + lr)      * D_DIM + k0 + lk);
        float4 a1 = *(const float4*)(x + (size_t)(m0 + lr + 64) * D_DIM + k0 + lk);
        float4 b0 = *(const float4*)(w + (size_t)(n0 + lr)      * D_DIM + k0 + lk);
        float4 b1 = *(const float4*)(w + (size_t)(n0 + lr + 64) * D_DIM + k0 + lk);
        __syncthreads();
        As[lk+0][lr]    = a0.x; As[lk+1][lr]    = a0.y; As[lk+2][lr]    = a0.z; As[lk+3][lr]    = a0.w;
        As[lk+0][lr+64] = a1.x; As[lk+1][lr+64] = a1.y; As[lk+2][lr+64] = a1.z; As[lk+3][lr+64] = a1.w;
        Bs[lk+0][lr]    = b0.x; Bs[lk+1][lr]    = b0.y; Bs[lk+2][lr]    = b0.z; Bs[lk+3][lr]    = b0.w;
        Bs[lk+0][lr+64] = b1.x; Bs[lk+1][lr+64] = b1.y; Bs[lk+2][lr+64] = b1.z; Bs[lk+3][lr+64] = b1.w;
        __syncthreads();
        #pragma unroll
        for (int kk = 0; kk < 16; kk++) {
            float a[8], b[8];
            *(float4*)(a)   = *(const float4*)(&As[kk][ty*8]);
            *(float4*)(a+4) = *(const float4*)(&As[kk][ty*8+4]);
            *(float4*)(b)   = *(const float4*)(&Bs[kk][tx*8]);
            *(float4*)(b+4) = *(const float4*)(&Bs[kk][tx*8+4]);
            #pragma unroll
            for (int i = 0; i < 8; i++)
                #pragma unroll
                for (int j = 0; j < 8; j++)
                    acc[i][j] = fmaf(a[i], b[j], acc[i][j]);
        }
    }

    const int m  = m0 + ty * 8;          // rows m..m+7 (same batch: 128 | 2048)
    const int bb = m >> 11;
    const int s  = m & (S_LEN - 1);

    if (blockIdx.z < 2) {
        // Q/K: write transposed [b,h,hd,s] — column j's 8 row-values are contiguous in s
        float* dst = (blockIdx.z == 0) ? g_q : g_k;
        #pragma unroll
        for (int j = 0; j < 8; j++) {
            int o = n0 + tx * 8 + j;
            int h = o >> 6, hd = o & 63;
            float* p = dst + (((size_t)bb * NH + h) * HDIM + hd) * S_LEN + s;
            *(float4*)(p)     = make_float4(acc[0][j], acc[1][j], acc[2][j], acc[3][j]);
            *(float4*)(p + 4) = make_float4(acc[4][j], acc[5][j], acc[6][j], acc[7][j]);
        }
    } else {
        // V: [b,h,s,hd] — row i's 8 col-values are contiguous in hd (stay in one head)
        int o = n0 + tx * 8;
        int h = o >> 6, hd = o & 63;
        #pragma unroll
        for (int i = 0; i < 8; i++) {
            float* p = g_v + (((size_t)bb * NH + h) * S_LEN + (s + i)) * HDIM + hd;
            *(float4*)(p)     = make_float4(acc[i][0], acc[i][1], acc[i][2], acc[i][3]);
            *(float4*)(p + 4) = make_float4(acc[i][4], acc[i][5], acc[i][6], acc[i][7]);
        }
    }
}

// ---------------------------------------------------------------------------
// Kernel 2: flash-style attention, unmasked softmax.
// grid = (S/128, B*H), 256 threads. CTA owns a 128-row Q tile of one (b,h).
// SMEM: Qs[64][128], Ks[64][128], Vs[128][68], PsT swizzled [128][128].
// ---------------------------------------------------------------------------
__global__ __launch_bounds__(256) void attn_kernel()
{
    extern __shared__ float sm[];
    float* Qs = sm;                  //  8192 floats, [d][s]  (Q pre-scaled by 1/8)
    float* Ks = Qs + 64 * 128;       //  8192 floats, [d][s]
    float* Vs = Ks + 64 * 128;       //  8704 floats, [kk][hd], stride 68
    float* Ps = Vs + 128 * 68;       // 16384 floats, P^T [col][row], XOR-swizzled chunks

    const int bh  = blockIdx.y;          // b*NH + h
    const int qt  = blockIdx.x;          // q tile
    const int tid = threadIdx.x;
    const int tx  = tid & 15, ty = tid >> 4;

    const float* qp = g_q + (size_t)bh * HDIM * S_LEN + qt * 128;
    const float* kp = g_k + (size_t)bh * HDIM * S_LEN;
    const float* vp = g_v + (size_t)bh * S_LEN * HDIM;

    // Load Q tile (64 x 128), fold in softmax scale 1/sqrt(64) = 0.125
    #pragma unroll
    for (int t = 0; t < 8; t++) {
        int u = tid + t * 256;                  // float4 index, 2048 total
        int d = u >> 5, c = (u & 31) << 2;
        float4 v4 = *(const float4*)(qp + (size_t)d * S_LEN + c);
        v4.x *= 0.125f; v4.y *= 0.125f; v4.z *= 0.125f; v4.w *= 0.125f;
        *(float4*)(Qs + d * 128 + c) = v4;
    }

    float m_i[8], l_i[8], o_acc[8][4];
    #pragma unroll
    for (int i = 0; i < 8; i++) {
        m_i[i] = -1e30f; l_i[i] = 0.f;
        #pragma unroll
        for (int j = 0; j < 4; j++) o_acc[i][j] = 0.f;
    }

    for (int kt = 0; kt < S_LEN / 128; kt++) {
        __syncthreads();   // previous iteration's Ps/Vs reads done before overwrite
        #pragma unroll
        for (int t = 0; t < 8; t++) {           // K tile [64][128]
            int u = tid + t * 256;
            int d = u >> 5, c = (u & 31) << 2;
            *(float4*)(Ks + d * 128 + c) =
                *(const float4*)(kp + (size_t)d * S_LEN + kt * 128 + c);
        }
        #pragma unroll
        for (int t = 0; t < 8; t++) {           // V tile [128][64] -> stride 68
            int u = tid + t * 256;
            int r = u >> 4, c = (u & 15) << 2;
            *(float4*)(Vs + r * 68 + c) =
                *(const float4*)(vp + (size_t)(kt * 128 + r) * HDIM + c);
        }
        __syncthreads();

        // S = (Q/8)^T K : 8x8 fragment per thread
        float acc[8][8];
        #pragma unroll
        for (int i = 0; i < 8; i++)
            #pragma unroll
            for (int j = 0; j < 8; j++) acc[i][j] = 0.f;

        #pragma unroll 4
        for (int d = 0; d < 64; d++) {
            float a[8], b[8];
            *(float4*)(a)   = *(const float4*)(Qs + d * 128 + ty * 8);
            *(float4*)(a+4) = *(const float4*)(Qs + d * 128 + ty * 8 + 4);
            *(float4*)(b)   = *(const float4*)(Ks + d * 128 + tx * 8);
            *(float4*)(b+4) = *(const float4*)(Ks + d * 128 + tx * 8 + 4);
            #pragma unroll
            for (int i = 0; i < 8; i++)
                #pragma unroll
                for (int j = 0; j < 8; j++)
                    acc[i][j] = fmaf(a[i], b[j], acc[i][j]);
        }

        // Online softmax update (rows shared by 16 lanes with same ty)
        #pragma unroll
        for (int i = 0; i < 8; i++) {
            float rm = acc[i][0];
            #pragma unroll
            for (int j = 1; j < 8; j++) rm = fmaxf(rm, acc[i][j]);
            #pragma unroll
            for (int off = 1; off < 16; off <<= 1)
                rm = fmaxf(rm, __shfl_xor_sync(0xffffffffu, rm, off));
            float mn   = fmaxf(m_i[i], rm);
            float corr = __expf(m_i[i] - mn);
            m_i[i] = mn;
            float rs = 0.f;
            #pragma unroll
            for (int j = 0; j < 8; j++) {
                float p = __expf(acc[i][j] - mn);
                acc[i][j] = p;
                rs += p;
            }
            #pragma unroll
            for (int off = 1; off < 16; off <<= 1)
                rs += __shfl_xor_sync(0xffffffffu, rs, off);
            l_i[i] = l_i[i] * corr + rs;
            #pragma unroll
            for (int j = 0; j < 4; j++) o_acc[i][j] *= corr;
        }

        // Store P^T [col][row] with XOR chunk swizzle: chunk' = chunk ^ ((col>>3)&7)
        {
            const int sw = tx & 7;               // (col>>3)&7 with col = tx*8+j, j<8
            #pragma unroll
            for (int j = 0; j < 8; j++) {
                float* base = Ps + (tx * 8 + j) * 128;
                *(float4*)(base + (((ty * 2 + 0) ^ sw) << 2)) =
                    make_float4(acc[0][j], acc[1][j], acc[2][j], acc[3][j]);
                *(float4*)(base + (((ty * 2 + 1) ^ sw) << 2)) =
                    make_float4(acc[4][j], acc[5][j], acc[6][j], acc[7][j]);
            }
        }
        __syncthreads();

        // O += P @ V : o_acc[i][jd] += P[row][kk] * V[kk][hd]
        #pragma unroll 4
        for (int kk = 0; kk < 128; kk++) {
            const int swk = (kk >> 3) & 7;
            float a[8], b[4];
            *(float4*)(a)   = *(const float4*)(Ps + kk * 128 + (((ty * 2 + 0) ^ swk) << 2));
            *(float4*)(a+4) = *(const float4*)(Ps + kk * 128 + (((ty * 2 + 1) ^ swk) << 2));
            *(float4*)(b)   = *(const float4*)(Vs + kk * 68 + tx * 4);
            #pragma unroll
            for (int i = 0; i < 8; i++)
                #pragma unroll
                for (int j = 0; j < 4; j++)
                    o_acc[i][j] = fmaf(a[i], b[j], o_acc[i][j]);
        }
    }

    // Normalize + write ctx [b,s,h,hd]
    const int b_ = bh >> 4, h = bh & 15;
    #pragma unroll
    for (int i = 0; i < 8; i++) {
        float inv = 1.f / l_i[i];
        int s = qt * 128 + ty * 8 + i;
        float* p = g_ctx + (((size_t)b_ * S_LEN + s) * NH + h) * HDIM + tx * 4;
        *(float4*)p = make_float4(o_acc[i][0] * inv, o_acc[i][1] * inv,
                                  o_acc[i][2] * inv, o_acc[i][3] * inv);
    }
}

// ---------------------------------------------------------------------------
// Kernel 3: output projection.  out[n,o] = sum_d ctx[n,d] * wo[o,d] + bo[o]
// ---------------------------------------------------------------------------
__global__ __launch_bounds__(256) void oproj_kernel(
    const float* __restrict__ wo, const float* __restrict__ bo,
    float* __restrict__ out)
{
    __shared__ float As[16][132];
    __shared__ float Bs[16][132];

    const int m0 = blockIdx.y * 128;
    const int n0 = blockIdx.x * 128;
    const int tid = threadIdx.x;
    const int tx = tid & 15, ty = tid >> 4;
    const int lr = tid >> 2, lk = (tid & 3) << 2;

    float acc[8][8];
    #pragma unroll
    for (int i = 0; i < 8; i++)
        #pragma unroll
        for (int j = 0; j < 8; j++) acc[i][j] = 0.f;

    for (int k0 = 0; k0 < D_DIM; k0 += 16) {
        float4 a0 = *(const float4*)(g_ctx + (size_t)(m0 + lr)      * D_DIM + k0 + lk);
        float4 a1 = *(const float4*)(g_ctx + (size_t)(m0 + lr + 64) * D_DIM + k0 + lk);
        float4 b0 = *(const float4*)(wo   + (size_t)(n0 + lr)      * D_DIM + k0 + lk);
        float4 b1 = *(const float4*)(wo   + (size_t)(n0 + lr + 64) * D_DIM + k0 + lk);
        __syncthreads();
        As[lk+0][lr]    = a0.x; As[lk+1][lr]    = a0.y; As[lk+2][lr]    = a0.z; As[lk+3][lr]    = a0.w;
        As[lk+0][lr+64] = a1.x; As[lk+1][lr+64] = a1.y; As[lk+2][lr+64] = a1.z; As[lk+3][lr+64] = a1.w;
        Bs[lk+0][lr]    = b0.x; Bs[lk+1][lr]    = b0.y; Bs[lk+2][lr]    = b0.z; Bs[lk+3][lr]    = b0.w;
        Bs[lk+0][lr+64] = b1.x; Bs[lk+1][lr+64] = b1.y; Bs[lk+2][lr+64] = b1.z; Bs[lk+3][lr+64] = b1.w;
        __syncthreads();
        #pragma unroll
        for (int kk = 0; kk < 16; kk++) {
            float a[8], b[8];
            *(float4*)(a)   = *(const float4*)(&As[kk][ty*8]);
            *(float4*)(a+4) = *(const float4*)(&As[kk][ty*8+4]);
            *(float4*)(b)   = *(const float4*)(&Bs[kk][tx*8]);
            *(float4*)(b+4) = *(const float4*)(&Bs[kk][tx*8+4]);
            #pragma unroll
            for (int i = 0; i < 8; i++)
                #pragma unroll
                for (int j = 0; j < 8; j++)
                    acc[i][j] = fmaf(a[i], b[j], acc[i][j]);
        }
    }

    float bias[8];
    *(float4*)(bias)   = *(const float4*)(bo + n0 + tx * 8);
    *(float4*)(bias+4) = *(const float4*)(bo + n0 + tx * 8 + 4);

    #pragma unroll
    for (int i = 0; i < 8; i++) {
        float* p = out + (size_t)(m0 + ty * 8 + i) * D_DIM + n0 + tx * 8;
        *(float4*)(p)     = make_float4(acc[i][0] + bias[0], acc[i][1] + bias[1],
                                        acc[i][2] + bias[2], acc[i][3] + bias[3]);
        *(float4*)(p + 4) = make_float4(acc[i][4] + bias[4], acc[i][5] + bias[5],
                                        acc[i][6] + bias[6], acc[i][7] + bias[7]);
    }
}

// ---------------------------------------------------------------------------
extern "C" void kernel_launch(void* const* d_in, const int* in_sizes, int n_in,
                              void* d_out, int out_size)
{
    const float* x  = (const float*)d_in[0];
    const float* wq = (const float*)d_in[1];
    const float* wk = (const float*)d_in[2];
    const float* wv = (const float*)d_in[3];
    const float* wo = (const float*)d_in[4];
    const float* bo = (const float*)d_in[5];
    float* out = (float*)d_out;

    const int attn_smem = (64*128 + 64*128 + 128*68 + 128*128) * sizeof(float); // 165888
    cudaFuncSetAttribute(attn_kernel, cudaFuncAttributeMaxDynamicSharedMemorySize, attn_smem);

    qkv_kernel<<<dim3(D_DIM/128, M_TOT/128, 3), 256>>>(x, wq, wk, wv);
    attn_kernel<<<dim3(S_LEN/128, NB*NH), 256, attn_smem>>>();
    oproj_kernel<<<dim3(D_DIM/128, M_TOT/128), 256>>>(wo, bo, out);
}

// round 2
// speedup vs baseline: 2.7612x; 2.7612x over previous
#include <cuda_runtime.h>
#include <cstdint>

#define S_LEN 2048
#define D_DIM 1024
#define NH    16
#define HDIM  64
#define NB    2
#define M_TOT 4096

// Scratch: Q/K/V in [b,h,s,hd] (Q pre-scaled by 0.125, all tf32-rounded), ctx in [b,s,d]
__device__ float g_q[NB * NH * S_LEN * HDIM];
__device__ float g_k[NB * NH * S_LEN * HDIM];
__device__ float g_v[NB * NH * S_LEN * HDIM];
__device__ float g_ctx[NB * S_LEN * D_DIM];

__device__ __forceinline__ uint32_t f2tf(float f) {
    uint32_t u;
    asm("cvt.rna.tf32.f32 %0, %1;" : "=r"(u) : "f"(f));
    return u;
}
__device__ __forceinline__ float u2f(uint32_t u) { return __uint_as_float(u); }
__device__ __forceinline__ uint32_t fbits(float f) { return __float_as_uint(f); }

__device__ __forceinline__ void mma_tf32(float d[4], const uint32_t a[4], const uint32_t b[2]) {
    asm("mma.sync.aligned.m16n8k8.row.col.f32.tf32.tf32.f32 "
        "{%0,%1,%2,%3}, {%4,%5,%6,%7}, {%8,%9}, {%0,%1,%2,%3};"
        : "+f"(d[0]), "+f"(d[1]), "+f"(d[2]), "+f"(d[3])
        : "r"(a[0]), "r"(a[1]), "r"(a[2]), "r"(a[3]), "r"(b[0]), "r"(b[1]));
}

// ---------------------------------------------------------------------------
// 128x128x1024 tile GEMM core (tf32 mma).  A[m][k], B[n][k] row-major ld=1024.
// 8 warps: 4(m) x 2(n); warp tile 32x64; k chunk 32, double-buffered SMEM.
// ---------------------------------------------------------------------------
#define PROJ_SMEM (2 * 128 * 36 * 2 * 4)   // 73728 B

__device__ __forceinline__ void ld_tile(const float* __restrict__ g, float4 v[4]) {
    const int tid = threadIdx.x;
    const int r = tid >> 3, c = (tid & 7) << 2;
    #pragma unroll
    for (int j = 0; j < 4; j++)
        v[j] = *(const float4*)(g + (size_t)(r + 32 * j) * D_DIM + c);
}
__device__ __forceinline__ void st_tile(float* s, const float4 v[4]) {
    const int tid = threadIdx.x;
    const int r = tid >> 3, c = (tid & 7) << 2;
    #pragma unroll
    for (int j = 0; j < 4; j++) {
        float* p = s + (r + 32 * j) * 36 + c;
        p[0] = u2f(f2tf(v[j].x)); p[1] = u2f(f2tf(v[j].y));
        p[2] = u2f(f2tf(v[j].z)); p[3] = u2f(f2tf(v[j].w));
    }
}

__device__ __forceinline__ void gemm128_core(
    const float* __restrict__ Ag, const float* __restrict__ Bg,
    float C[2][8][4], float* sm)
{
    float* As = sm;                    // 2 x 128 x 36
    float* Bs = sm + 2 * 128 * 36;
    const int tid = threadIdx.x, wid = tid >> 5, lane = tid & 31;
    const int gq = lane >> 2, qi = lane & 3;
    const int wm = (wid >> 1) * 32, wn = (wid & 1) * 64;

    #pragma unroll
    for (int mi = 0; mi < 2; mi++)
        #pragma unroll
        for (int nt = 0; nt < 8; nt++)
            #pragma unroll
            for (int r = 0; r < 4; r++) C[mi][nt][r] = 0.f;

    float4 pa[4], pb[4];
    ld_tile(Ag, pa); ld_tile(Bg, pb);
    st_tile(As, pa); st_tile(Bs, pb);
    __syncthreads();

    for (int ch = 0; ch < 32; ch++) {
        if (ch < 31) {
            ld_tile(Ag + (ch + 1) * 32, pa);
            ld_tile(Bg + (ch + 1) * 32, pb);
        }
        const float* as = As + (ch & 1) * (128 * 36);
        const float* bs = Bs + (ch & 1) * (128 * 36);
        #pragma unroll
        for (int ks = 0; ks < 4; ks++) {
            uint32_t a[2][4];
            #pragma unroll
            for (int mi = 0; mi < 2; mi++) {
                const float* p = as + (wm + 16 * mi + gq) * 36 + 8 * ks + qi;
                a[mi][0] = fbits(p[0]);
                a[mi][1] = fbits(p[8 * 36]);
                a[mi][2] = fbits(p[4]);
                a[mi][3] = fbits(p[8 * 36 + 4]);
            }
            #pragma unroll
            for (int nt = 0; nt < 8; nt++) {
                const float* p = bs + (wn + 8 * nt + gq) * 36 + 8 * ks + qi;
                uint32_t b[2] = { fbits(p[0]), fbits(p[4]) };
                mma_tf32(C[0][nt], a[0], b);
                mma_tf32(C[1][nt], a[1], b);
            }
        }
        if (ch < 31) {
            st_tile(As + ((ch + 1) & 1) * (128 * 36), pa);
            st_tile(Bs + ((ch + 1) & 1) * (128 * 36), pb);
            __syncthreads();
        }
    }
}

// ---------------------------------------------------------------------------
// Kernel 1: fused QKV projection -> g_q/g_k/g_v in [b,h,s,hd] (tf32-rounded)
// ---------------------------------------------------------------------------
__global__ __launch_bounds__(256, 1) void qkv_kernel(
    const float* __restrict__ x,  const float* __restrict__ wq,
    const float* __restrict__ wk, const float* __restrict__ wv)
{
    extern __shared__ float sm[];
    const int m0 = blockIdx.y * 128, n0 = blockIdx.x * 128, z = blockIdx.z;
    const float* w = (z == 0) ? wq : ((z == 1) ? wk : wv);

    float C[2][8][4];
    gemm128_core(x + (size_t)m0 * D_DIM, w + (size_t)n0 * D_DIM, C, sm);

    float* dst = (z == 0) ? g_q : ((z == 1) ? g_k : g_v);
    const float scale = (z == 0) ? 0.125f : 1.0f;   // fold 1/sqrt(64) into Q

    const int tid = threadIdx.x, wid = tid >> 5, lane = tid & 31;
    const int gq = lane >> 2, qi = lane & 3;
    const int wm = (wid >> 1) * 32, wn = (wid & 1) * 64;

    #pragma unroll
    for (int mi = 0; mi < 2; mi++)
        #pragma unroll
        for (int nt = 0; nt < 8; nt++) {
            int m = m0 + wm + 16 * mi + gq;
            int n = n0 + wn + 8 * nt + 2 * qi;
            int h = n >> 6, hd = n & 63, bb = m >> 11, s = m & (S_LEN - 1);
            float* p0 = dst + (((size_t)bb * NH + h) * S_LEN + s) * HDIM + hd;
            float* p1 = dst + (((size_t)bb * NH + h) * S_LEN + s + 8) * HDIM + hd;
            *(float2*)p0 = make_float2(u2f(f2tf(C[mi][nt][0] * scale)),
                                       u2f(f2tf(C[mi][nt][1] * scale)));
            *(float2*)p1 = make_float2(u2f(f2tf(C[mi][nt][2] * scale)),
                                       u2f(f2tf(C[mi][nt][3] * scale)));
        }
}

// ---------------------------------------------------------------------------
// Kernel 2: flash attention (unmasked), tf32 mma for QK^T and PV.
// grid=(16, B*H), 256 thr. Warps 4(m)x2(n): S warp tile 32x64, O tile 32x32.
// ---------------------------------------------------------------------------
#define ATTN_SMEM ((128*68 + 128*68 + 128*72 + 128*132 + 512) * 4)  // 176128 B

__global__ __launch_bounds__(256, 1) void attn_kernel()
{
    extern __shared__ float sm[];
    float* Qs   = sm;                    // [128][68]
    float* Ks   = Qs + 128 * 68;         // [128][68]
    float* Vs   = Ks + 128 * 68;         // [128][72]
    float* Ps   = Vs + 128 * 72;         // [128][132]
    float* redm = Ps + 128 * 132;        // [2][128]
    float* reds = redm + 256;            // [2][128]

    const int bh = blockIdx.y, qt = blockIdx.x;
    const int tid = threadIdx.x, wid = tid >> 5, lane = tid & 31;
    const int gq = lane >> 2, qi = lane & 3;
    const int wm = (wid >> 1) * 32;
    const int nh = wid & 1;
    const int wn = nh * 64;     // S column offset (kpos)
    const int wo = nh * 32;     // O column offset (hd)

    const float* qp = g_q + ((size_t)bh * S_LEN + qt * 128) * HDIM;
    const float* kp = g_k + (size_t)bh * S_LEN * HDIM;
    const float* vp = g_v + (size_t)bh * S_LEN * HDIM;

    // Load Q tile (already scaled + tf32-rounded in gmem)
    {
        const int r = tid >> 4, c = (tid & 15) << 2;
        #pragma unroll
        for (int j = 0; j < 8; j++)
            *(float4*)(Qs + (r + 16 * j) * 68 + c) =
                *(const float4*)(qp + (size_t)(r + 16 * j) * HDIM + c);
    }

    float O[2][4][4];
    float m_i[4], l_i[4];
    #pragma unroll
    for (int i = 0; i < 4; i++) { m_i[i] = -1e30f; l_i[i] = 0.f; }
    #pragma unroll
    for (int mi = 0; mi < 2; mi++)
        #pragma unroll
        for (int ni = 0; ni < 4; ni++)
            #pragma unroll
            for (int r = 0; r < 4; r++) O[mi][ni][r] = 0.f;

    #pragma unroll 1
    for (int kt = 0; kt < S_LEN / 128; kt++) {
        __syncthreads();   // previous iter's Ks/Vs/Ps reads complete
        {
            const int r = tid >> 4, c = (tid & 15) << 2;
            #pragma unroll
            for (int j = 0; j < 8; j++) {
                *(float4*)(Ks + (r + 16 * j) * 68 + c) =
                    *(const float4*)(kp + (size_t)(kt * 128 + r + 16 * j) * HDIM + c);
                *(float4*)(Vs + (r + 16 * j) * 72 + c) =
                    *(const float4*)(vp + (size_t)(kt * 128 + r + 16 * j) * HDIM + c);
            }
        }
        __syncthreads();

        // S = Q @ K^T  (warp: rows wm..wm+31, cols wn..wn+63)
        float Cs[2][8][4];
        #pragma unroll
        for (int mi = 0; mi < 2; mi++)
            #pragma unroll
            for (int nt = 0; nt < 8; nt++)
                #pragma unroll
                for (int r = 0; r < 4; r++) Cs[mi][nt][r] = 0.f;

        #pragma unroll
        for (int ks = 0; ks < 8; ks++) {
            uint32_t a[2][4];
            #pragma unroll
            for (int mi = 0; mi < 2; mi++) {
                const float* p = Qs + (wm + 16 * mi + gq) * 68 + 8 * ks + qi;
                a[mi][0] = fbits(p[0]);
                a[mi][1] = fbits(p[8 * 68]);
                a[mi][2] = fbits(p[4]);
                a[mi][3] = fbits(p[8 * 68 + 4]);
            }
            #pragma unroll
            for (int nt = 0; nt < 8; nt++) {
                const float* p = Ks + (wn + 8 * nt + gq) * 68 + 8 * ks + qi;
                uint32_t b[2] = { fbits(p[0]), fbits(p[4]) };
                mma_tf32(Cs[0][nt], a[0], b);
                mma_tf32(Cs[1][nt], a[1], b);
            }
        }

        // Partial row max (warp covers 64 of 128 cols) + cross-warp combine
        #pragma unroll
        for (int i = 0; i < 4; i++) {
            int mi = i >> 1, hf = i & 1;
            float v = Cs[mi][0][2 * hf];
            #pragma unroll
            for (int nt = 0; nt < 8; nt++) {
                v = fmaxf(v, Cs[mi][nt][2 * hf]);
                v = fmaxf(v, Cs[mi][nt][2 * hf + 1]);
            }
            v = fmaxf(v, __shfl_xor_sync(0xffffffffu, v, 1));
            v = fmaxf(v, __shfl_xor_sync(0xffffffffu, v, 2));
            if (qi == 0) redm[nh * 128 + wm + 16 * mi + 8 * hf + gq] = v;
        }
        __syncthreads();

        float mn[4], corr[4];
        #pragma unroll
        for (int i = 0; i < 4; i++) {
            int row = wm + 16 * (i >> 1) + 8 * (i & 1) + gq;
            float gm = fmaxf(redm[row], redm[128 + row]);
            mn[i] = fmaxf(m_i[i], gm);
            corr[i] = __expf(m_i[i] - mn[i]);
            m_i[i] = mn[i];
        }

        // exp + partial row sums
        float ps[4] = {0.f, 0.f, 0.f, 0.f};
        #pragma unroll
        for (int mi = 0; mi < 2; mi++)
            #pragma unroll
            for (int nt = 0; nt < 8; nt++)
                #pragma unroll
                for (int hf = 0; hf < 2; hf++) {
                    float e0 = __expf(Cs[mi][nt][2 * hf]     - mn[2 * mi + hf]);
                    float e1 = __expf(Cs[mi][nt][2 * hf + 1] - mn[2 * mi + hf]);
                    Cs[mi][nt][2 * hf] = e0; Cs[mi][nt][2 * hf + 1] = e1;
                    ps[2 * mi + hf] += e0 + e1;
                }
        #pragma unroll
        for (int i = 0; i < 4; i++) {
            float v = ps[i];
            v += __shfl_xor_sync(0xffffffffu, v, 1);
            v += __shfl_xor_sync(0xffffffffu, v, 2);
            if (qi == 0) reds[nh * 128 + wm + 16 * (i >> 1) + 8 * (i & 1) + gq] = v;
        }

        // rescale O by corr
        #pragma unroll
        for (int mi = 0; mi < 2; mi++)
            #pragma unroll
            for (int ni = 0; ni < 4; ni++) {
                O[mi][ni][0] *= corr[2 * mi];     O[mi][ni][1] *= corr[2 * mi];
                O[mi][ni][2] *= corr[2 * mi + 1]; O[mi][ni][3] *= corr[2 * mi + 1];
            }

        // store P (tf32-rounded) to SMEM
        #pragma unroll
        for (int mi = 0; mi < 2; mi++)
            #pragma unroll
            for (int nt = 0; nt < 8; nt++) {
                int row = wm + 16 * mi + gq, col = wn + 8 * nt + 2 * qi;
                *(float2*)(Ps + row * 132 + col) =
                    make_float2(u2f(f2tf(Cs[mi][nt][0])), u2f(f2tf(Cs[mi][nt][1])));
                *(float2*)(Ps + (row + 8) * 132 + col) =
                    make_float2(u2f(f2tf(Cs[mi][nt][2])), u2f(f2tf(Cs[mi][nt][3])));
            }
        __syncthreads();

        #pragma unroll
        for (int i = 0; i < 4; i++) {
            int row = wm + 16 * (i >> 1) + 8 * (i & 1) + gq;
            l_i[i] = l_i[i] * corr[i] + reds[row] + reds[128 + row];
        }

        // O += P @ V  (warp: rows wm..wm+31, hd cols wo..wo+31)
        #pragma unroll
        for (int ks = 0; ks < 16; ks++) {
            uint32_t a[2][4];
            #pragma unroll
            for (int mi = 0; mi < 2; mi++) {
                const float* p = Ps + (wm + 16 * mi + gq) * 132 + 8 * ks + qi;
                a[mi][0] = fbits(p[0]);
                a[mi][1] = fbits(p[8 * 132]);
                a[mi][2] = fbits(p[4]);
                a[mi][3] = fbits(p[8 * 132 + 4]);
            }
            #pragma unroll
            for (int ni = 0; ni < 4; ni++) {
                const float* p = Vs + (size_t)(8 * ks + qi) * 72 + wo + 8 * ni + gq;
                uint32_t b[2] = { fbits(p[0]), fbits(p[4 * 72]) };
                mma_tf32(O[0][ni], a[0], b);
                mma_tf32(O[1][ni], a[1], b);
            }
        }
    }

    // epilogue: normalize + write ctx [b,s,h,hd]
    const int b_ = bh >> 4, h = bh & 15;
    #pragma unroll
    for (int mi = 0; mi < 2; mi++) {
        float inv0 = 1.f / l_i[2 * mi], inv1 = 1.f / l_i[2 * mi + 1];
        int s = qt * 128 + wm + 16 * mi + gq;
        #pragma unroll
        for (int ni = 0; ni < 4; ni++) {
            int cc = wo + 8 * ni + 2 * qi;
            float* p0 = g_ctx + (((size_t)b_ * S_LEN + s) * NH + h) * HDIM + cc;
            float* p1 = g_ctx + (((size_t)b_ * S_LEN + s + 8) * NH + h) * HDIM + cc;
            *(float2*)p0 = make_float2(O[mi][ni][0] * inv0, O[mi][ni][1] * inv0);
            *(float2*)p1 = make_float2(O[mi][ni][2] * inv1, O[mi][ni][3] * inv1);
        }
    }
}

// ---------------------------------------------------------------------------
// Kernel 3: output projection + bias
// ---------------------------------------------------------------------------
__global__ __launch_bounds__(256, 1) void oproj_kernel(
    const float* __restrict__ wo, const float* __restrict__ bo,
    float* __restrict__ out)
{
    extern __shared__ float sm[];
    const int m0 = blockIdx.y * 128, n0 = blockIdx.x * 128;

    float C[2][8][4];
    gemm128_core(g_ctx + (size_t)m0 * D_DIM, wo + (size_t)n0 * D_DIM, C, sm);

    const int tid = threadIdx.x, wid = tid >> 5, lane = tid & 31;
    const int gq = lane >> 2, qi = lane & 3;
    const int wm = (wid >> 1) * 32, wn = (wid & 1) * 64;

    #pragma unroll
    for (int mi = 0; mi < 2; mi++)
        #pragma unroll
        for (int nt = 0; nt < 8; nt++) {
            int m = m0 + wm + 16 * mi + gq;
            int n = n0 + wn + 8 * nt + 2 * qi;
            float b0 = bo[n], b1 = bo[n + 1];
            *(float2*)(out + (size_t)m * D_DIM + n) =
                make_float2(C[mi][nt][0] + b0, C[mi][nt][1] + b1);
            *(float2*)(out + (size_t)(m + 8) * D_DIM + n) =
                make_float2(C[mi][nt][2] + b0, C[mi][nt][3] + b1);
        }
}

// ---------------------------------------------------------------------------
extern "C" void kernel_launch(void* const* d_in, const int* in_sizes, int n_in,
                              void* d_out, int out_size)
{
    const float* x  = (const float*)d_in[0];
    const float* wq = (const float*)d_in[1];
    const float* wk = (const float*)d_in[2];
    const float* wv = (const float*)d_in[3];
    const float* wo = (const float*)d_in[4];
    const float* bo = (const float*)d_in[5];
    float* out = (float*)d_out;

    cudaFuncSetAttribute(qkv_kernel,   cudaFuncAttributeMaxDynamicSharedMemorySize, PROJ_SMEM);
    cudaFuncSetAttribute(oproj_kernel, cudaFuncAttributeMaxDynamicSharedMemorySize, PROJ_SMEM);
    cudaFuncSetAttribute(attn_kernel,  cudaFuncAttributeMaxDynamicSharedMemorySize, ATTN_SMEM);

    qkv_kernel<<<dim3(D_DIM / 128, M_TOT / 128, 3), 256, PROJ_SMEM>>>(x, wq, wk, wv);
    attn_kernel<<<dim3(S_LEN / 128, NB * NH), 256, ATTN_SMEM>>>();
    oproj_kernel<<<dim3(D_DIM / 128, M_TOT / 128), 256, PROJ_SMEM>>>(wo, bo, out);
}